// round 14
// baseline (speedup 1.0000x reference)
#include <cuda_runtime.h>
#include <math.h>
#include <float.h>

// ---------------- problem constants ----------------
#define Gg    2
#define NPn   332
#define NN    664
#define NE    21248
#define FD    332
#define KD    2324          // 7*FD : 6 W2 slices + nb channel
#define W2SZ  (FD*FD)
#define KP1   166
#define KP2   83
#define ZDIM  1328
#define DD3   128
#define BM    64
#define BN    64
#define BK    16
#define KSPL  16

// ---------------- packed fp32x2 helpers ----------------
#define FMA2(acc, a2, b2) asm("fma.rn.f32x2 %0, %1, %2, %0;" : "+l"(acc) : "l"(a2), "l"(b2))
#define PACK2(d, f)       asm("mov.b64 %0, {%1, %1};" : "=l"(d) : "r"(__float_as_uint(f)))
#define UNPACK2(lo, hi, v) asm("mov.b64 {%0, %1}, %2;" : "=r"(lo), "=r"(hi) : "l"(v))

// ---------------- scratch ----------------
__device__ __align__(16) float g_part[KSPL * NN * FD]; // split-K partials
__device__ __align__(16) float g_xt [NN * FD];
__device__ __align__(16) float g_h1 [NN * FD];
__device__ __align__(16) float g_hp1[Gg*KP1 * FD];
__device__ __align__(16) float g_h2 [NN * FD];
__device__ float g_dp [2 * NN];        // per-half TopK dot partials
__device__ float g_sc [Gg * 256];
__device__ int   g_si [Gg * 256];
__device__ int   g_perm1 [Gg*KP1];
__device__ int   g_newidx1[NN];
__device__ int   g_tilecnt[66];        // split-K completion counters (self-resetting)
__device__ int   g_csr_ptr[NN + 1];
__device__ int   g_csr_eid[NE];
__device__ int   g_csr_src[NE];
__device__ float g_invn[2];
__device__ float g_z  [Gg * ZDIM];

// ======== conv GEMM: 64x64 tile, 8x4/thread, FFMA2, split-K =============
//  + fused CSR build (blockIdx.z == KSPL, one 128-thread block)
//  + fused split-K reduction (last finisher per tile, fixed z-order)
// partial[z][M,332] = A_z[M,*]@B_z ; A[m,kk*332+ki] = X[m,ki]*h6[m,kk]
// h6[m,:] = relu(W1[rowid(m),:]) (+1 for nb channel), pos == tile(eye(332)).
template<int STAGE>
__global__ void __launch_bounds__(128, 8) k_gemm(const float* __restrict__ Xin,
        const float* __restrict__ W1, const float* __restrict__ W2,
        const float* __restrict__ nb, const int* __restrict__ ei,
        const float* __restrict__ pw)
{
    constexpr int M = STAGE ? (Gg * KP1) : NN;
    constexpr int NDST = STAGE ? (Gg * KP1) : NN;
    const int tid = threadIdx.x;

    // ---------- fused CSR block ----------
    if (blockIdx.z == KSPL) {
        if (blockIdx.x != 0 || blockIdx.y != 0) return;
        __shared__ int   cnt [NN];
        __shared__ int   slot[NN];
        __shared__ float red [128];
        __shared__ int   wsum[128];
        // pw norm
        float p = 0.f;
        for (int i = tid; i < FD; i += 128) p += pw[i] * pw[i];
        red[tid] = p; __syncthreads();
        for (int s = 64; s; s >>= 1) { if (tid < s) red[tid] += red[tid + s]; __syncthreads(); }
        if (tid == 0) g_invn[STAGE] = rsqrtf(red[0]);
        // count
        for (int i = tid; i < NDST; i += 128) { cnt[i] = 0; slot[i] = 0; }
        __syncthreads();
        const int* srcA = ei;
        const int* dstA = ei + NE;
        for (int e = tid; e < NE; e += 128) {
            int d = dstA[e];
            if (STAGE) {
                int ns = g_newidx1[srcA[e]];
                int nd = g_newidx1[d];
                if (ns < 0 || nd < 0) continue;
                d = nd;
            }
            atomicAdd(&cnt[d], 1);
        }
        __syncthreads();
        // exclusive scan (chunked)
        constexpr int PER = (NDST + 127) / 128;
        int base = tid * PER, loc = 0;
#pragma unroll
        for (int j = 0; j < PER; j++) {
            int idx = base + j;
            if (idx < NDST) { int v = cnt[idx]; cnt[idx] = loc; loc += v; }
        }
        wsum[tid] = loc; __syncthreads();
        for (int off = 1; off < 128; off <<= 1) {
            int v = (tid >= off) ? wsum[tid - off] : 0;
            __syncthreads();
            wsum[tid] += v;
            __syncthreads();
        }
        int add = tid ? wsum[tid - 1] : 0;
#pragma unroll
        for (int j = 0; j < PER; j++) {
            int idx = base + j;
            if (idx < NDST) cnt[idx] += add;
        }
        __syncthreads();
        for (int i = tid; i < NDST; i += 128) g_csr_ptr[i] = cnt[i];
        if (tid == 0) g_csr_ptr[NDST] = wsum[127];
        // fill
        for (int e = tid; e < NE; e += 128) {
            int s = srcA[e], d = dstA[e];
            if (STAGE) {
                s = g_newidx1[s];
                int nd = g_newidx1[d];
                if (s < 0 || nd < 0) continue;
                d = nd;
            }
            int pidx = cnt[d] + atomicAdd(&slot[d], 1);
            g_csr_eid[pidx] = e;
            g_csr_src[pidx] = s;
        }
        return;
    }

    // ---------- GEMM path ----------
    const float* X = STAGE ? (const float*)g_hp1 : Xin;
    __shared__ __align__(16) float As[2][BK][BM + 4];   // pitch 272B
    __shared__ __align__(16) float Bs[2][BK][BN + 4];
    __shared__ float h6s[BM][9];                        // pitch 9: lane reads conflict-free
    const int tx   = tid & 15, ty = tid >> 4;           // 16 x 8
    const int lane = tid & 31, w  = tid >> 5;
    const int row0 = blockIdx.y * BM, col0 = blockIdx.x * BN;

    for (int l = tid; l < BM * 8; l += 128) {
        int m = l >> 3, k = l & 7;
        int r = row0 + m; if (r >= M) r = M - 1;
        float v = 0.f;
        if (k == 6) v = 1.f;
        else if (k < 6) {
            int rid = STAGE ? (g_perm1[r] % NPn) : (r % NPn);
            v = fmaxf(W1[rid * 6 + k], 0.f);
        }
        h6s[m][k] = v;
    }
    __syncthreads();

    const int  rA0 = row0 + lane, rA1 = row0 + lane + 32;
    const bool ok0 = (rA0 < M), ok1 = (rA1 < M);

    constexpr int NCH = (KD + BK - 1) / BK;        // 146
    const int z    = blockIdx.z;
    const int cbeg = (NCH * z) / KSPL;
    const int cend = (NCH * (z + 1)) / KSPL;

    const int kB = tid >> 3, nB = (tid & 7) << 3;

    auto load_tile = [&](int c, int buf) {
        // ---- A tile (64 x 16) ----
        int kg0 = c * BK + 4 * w;
        float4 x0 = make_float4(0.f,0.f,0.f,0.f), x1 = x0;
        float  h0 = 0.f, h1 = 0.f;
        if (kg0 < KD) {
            int kk  = kg0 / FD;
            int ki0 = kg0 - kk * FD;
            if (ok0) x0 = *(const float4*)(X + (size_t)rA0 * FD + ki0);
            if (ok1) x1 = *(const float4*)(X + (size_t)rA1 * FD + ki0);
            h0 = h6s[lane][kk]; h1 = h6s[lane + 32][kk];
        }
        As[buf][4*w + 0][lane]      = x0.x * h0;
        As[buf][4*w + 1][lane]      = x0.y * h0;
        As[buf][4*w + 2][lane]      = x0.z * h0;
        As[buf][4*w + 3][lane]      = x0.w * h0;
        As[buf][4*w + 0][lane + 32] = x1.x * h1;
        As[buf][4*w + 1][lane + 32] = x1.y * h1;
        As[buf][4*w + 2][lane + 32] = x1.z * h1;
        As[buf][4*w + 3][lane + 32] = x1.w * h1;
        // ---- B tile (16 x 64) ----
        int kg = c * BK + kB;
        float4 v0 = make_float4(0.f,0.f,0.f,0.f), v1 = v0;
        if (kg < KD) {
            int kkb = kg / FD, ki = kg - kkb * FD;
            const float* bp = (kkb < 6) ? (W2 + (size_t)kkb * W2SZ + (size_t)ki * FD)
                                        : (nb + (size_t)ki * FD);
            int cA = col0 + nB;
            if (cA + 3 < FD) v0 = *(const float4*)(bp + cA);
            if (cA + 7 < FD) v1 = *(const float4*)(bp + cA + 4);
        }
        *(float4*)&Bs[buf][kB][nB]     = v0;
        *(float4*)&Bs[buf][kB][nB + 4] = v1;
    };

    unsigned long long acc[8][2] = {};
    load_tile(cbeg, 0);
    __syncthreads();
    for (int c = cbeg; c < cend; c++) {
        int buf = (c - cbeg) & 1;
        if (c + 1 < cend) load_tile(c + 1, buf ^ 1);
#pragma unroll
        for (int kk = 0; kk < BK; kk++) {
            ulonglong2 bv = *(const ulonglong2*)&Bs[buf][kk][tx << 2];
            float4 a0 = *(const float4*)&As[buf][kk][ty << 3];       // broadcast
            float4 a1 = *(const float4*)&As[buf][kk][(ty << 3) + 4];
            unsigned long long p0,p1,p2,p3,p4,p5,p6,p7;
            PACK2(p0, a0.x); PACK2(p1, a0.y); PACK2(p2, a0.z); PACK2(p3, a0.w);
            PACK2(p4, a1.x); PACK2(p5, a1.y); PACK2(p6, a1.z); PACK2(p7, a1.w);
            FMA2(acc[0][0], p0, bv.x); FMA2(acc[0][1], p0, bv.y);
            FMA2(acc[1][0], p1, bv.x); FMA2(acc[1][1], p1, bv.y);
            FMA2(acc[2][0], p2, bv.x); FMA2(acc[2][1], p2, bv.y);
            FMA2(acc[3][0], p3, bv.x); FMA2(acc[3][1], p3, bv.y);
            FMA2(acc[4][0], p4, bv.x); FMA2(acc[4][1], p4, bv.y);
            FMA2(acc[5][0], p5, bv.x); FMA2(acc[5][1], p5, bv.y);
            FMA2(acc[6][0], p6, bv.x); FMA2(acc[6][1], p6, bv.y);
            FMA2(acc[7][0], p7, bv.x); FMA2(acc[7][1], p7, bv.y);
        }
        __syncthreads();
    }

    int cc = col0 + (tx << 2);
    if (cc + 3 < FD) {
        float* base = &g_part[(size_t)z * M * FD];
#pragma unroll
        for (int j = 0; j < 8; j++) {
            int r = row0 + (ty << 3) + j;
            if (r < M) {
                unsigned int x0,x1,x2,x3;
                UNPACK2(x0, x1, acc[j][0]);
                UNPACK2(x2, x3, acc[j][1]);
                *(float4*)&base[(size_t)r * FD + cc] = make_float4(
                    __uint_as_float(x0), __uint_as_float(x1),
                    __uint_as_float(x2), __uint_as_float(x3));
            }
        }
    }

    // ---------- fused split-K reduction: last finisher per tile ----------
    __threadfence();
    __syncthreads();
    __shared__ int is_last;
    if (tid == 0) {
        int tile = blockIdx.y * gridDim.x + blockIdx.x;
        int old = atomicAdd(&g_tilecnt[tile], 1);
        is_last = (old == KSPL - 1);
        if (is_last) g_tilecnt[tile] = 0;       // reset for next replay
    }
    __syncthreads();
    if (!is_last) return;
    __threadfence();
    for (int i = tid; i < (BM * BN) / 4; i += 128) {
        int rr = i / (BN / 4);
        int c4 = (i - rr * (BN / 4)) * 4;
        int r = row0 + rr, c2 = col0 + c4;
        if (r < M && c2 + 3 < FD) {
            float4 s = make_float4(0.f, 0.f, 0.f, 0.f);
#pragma unroll
            for (int zz = 0; zz < KSPL; zz++) {
                float4 v = *(const float4*)&g_part[(size_t)zz * M * FD + (size_t)r * FD + c2];
                s.x += v.x; s.y += v.y; s.z += v.z; s.w += v.w;
            }
            *(float4*)&g_xt[(size_t)r * FD + c2] = s;
        }
    }
}

// ======== softmax aggregation (col-split) + TopK dot partial ============
// grid (n_dst, 2); block handles cols [half*166, half*166+166)
__global__ void k_agg(int outsel, const float* __restrict__ eattr,
                      const float* __restrict__ bias, const float* __restrict__ pw)
{
    int d    = blockIdx.x;
    int half = blockIdx.y;
    int t = threadIdx.x;                 // 128
    __shared__ float sred[128];
    __shared__ float ws[128];
    __shared__ int   ss[128];

    int begin = g_csr_ptr[d], end = g_csr_ptr[d + 1];
    int deg = end - begin;

    float m = 1.0f;                      // self-loop logit
    for (int e = begin + t; e < end; e += 128) m = fmaxf(m, eattr[g_csr_eid[e]]);
    sred[t] = m; __syncthreads();
    for (int s = 64; s; s >>= 1) { if (t < s) sred[t] = fmaxf(sred[t], sred[t + s]); __syncthreads(); }
    m = sred[0]; __syncthreads();

    float se = 0.f;
    for (int e = begin + t; e < end; e += 128) se += expf(eattr[g_csr_eid[e]] - m);
    sred[t] = se; __syncthreads();
    for (int s = 64; s; s >>= 1) { if (t < s) sred[t] += sred[t + s]; __syncthreads(); }
    float selfe = expf(1.0f - m);
    float inv = 1.f / (sred[0] + selfe);
    float selfw = selfe * inv;
    __syncthreads();

    const int base = half * 166;
    const int o0 = base + t;             // always < 332
    const int o1 = base + 128 + t;       // valid for t < 38
    const bool has1 = (t < 38);
    const float* xd = &g_xt[(size_t)d * FD];
    float acc0 = selfw * xd[o0];
    float acc1 = has1 ? selfw * xd[o1] : 0.f;

    for (int c0 = 0; c0 < deg; c0 += 128) {
        if (c0 + t < deg) {
            int e = begin + c0 + t;
            ws[t] = expf(eattr[g_csr_eid[e]] - m) * inv;
            ss[t] = g_csr_src[e];
        }
        __syncthreads();
        int cn = min(128, deg - c0);
        int q = 0;
        for (; q + 4 <= cn; q += 4) {
            const float* x0 = &g_xt[(size_t)ss[q]   * FD];
            const float* x1 = &g_xt[(size_t)ss[q+1] * FD];
            const float* x2 = &g_xt[(size_t)ss[q+2] * FD];
            const float* x3 = &g_xt[(size_t)ss[q+3] * FD];
            float w0 = ws[q], w1 = ws[q+1], w2 = ws[q+2], w3 = ws[q+3];
            acc0 += w0*x0[o0] + w1*x1[o0] + w2*x2[o0] + w3*x3[o0];
            if (has1) acc1 += w0*x0[o1] + w1*x1[o1] + w2*x2[o1] + w3*x3[o1];
        }
        for (; q < cn; q++) {
            float wv = ws[q];
            const float* xr = &g_xt[(size_t)ss[q] * FD];
            acc0 += wv * xr[o0];
            if (has1) acc1 += wv * xr[o1];
        }
        __syncthreads();
    }
    acc0 += bias[o0];
    if (has1) acc1 += bias[o1];
    float* out = outsel ? g_h2 : g_h1;
    out[(size_t)d * FD + o0] = acc0;
    if (has1) out[(size_t)d * FD + o1] = acc1;

    // partial TopK dot for this column half
    float dp = acc0 * pw[o0] + (has1 ? acc1 * pw[o1] : 0.f);
    sred[t] = dp; __syncthreads();
    for (int s = 64; s; s >>= 1) { if (t < s) sred[t] += sred[t + s]; __syncthreads(); }
    if (t == 0) g_dp[half * NN + d] = sred[0];
}

// ======== sort: combine dot partials -> score -> bitonic ================
template<int STAGE>
__global__ void k_sort()
{
    constexpr int n_per = (STAGE == 1) ? NPn : KP1;
    constexpr int K     = (STAGE == 1) ? KP1 : KP2;
    int g = blockIdx.x;
    int t = threadIdx.x;                 // 512
    __shared__ float sc[512];
    __shared__ int   si[512];
    float invn = g_invn[STAGE - 1];
    if (t < n_per) {
        int node = g * n_per + t;
        float dp = g_dp[node] + g_dp[NN + node];
        sc[t] = 1.f / (1.f + expf(-dp * invn));
        si[t] = t;
    } else { sc[t] = -FLT_MAX; si[t] = 100000 + t; }
    __syncthreads();

    for (int k = 2; k <= 512; k <<= 1) {
        for (int j = k >> 1; j; j >>= 1) {
            int ixj = t ^ j;
            if (ixj > t) {
                float a = sc[t], b2 = sc[ixj];
                int ia = si[t], ib = si[ixj];
                bool afirst = (a > b2) || (a == b2 && ia < ib);
                bool up = ((t & k) == 0);
                if (up ? !afirst : afirst) { sc[t] = b2; sc[ixj] = a; si[t] = ib; si[ixj] = ia; }
            }
            __syncthreads();
        }
    }
    if (t < K) { g_si[g * 256 + t] = si[t]; g_sc[g * 256 + t] = sc[t]; }
    if (STAGE == 1) {
        if (t < n_per) g_newidx1[g * n_per + t] = -1;
        __syncthreads();
        if (t < K) {
            g_newidx1[g * n_per + si[t]] = g * K + t;
            g_perm1[g * K + t] = g * n_per + si[t];
        }
    }
}

// ======== wide-grid post: readout (+hp1 for stage 1) ====================
template<int STAGE>
__global__ void __launch_bounds__(256) k_post()
{
    constexpr int n_per = (STAGE == 1) ? NPn : KP1;
    constexpr int K     = (STAGE == 1) ? KP1 : KP2;
    constexpr int zoff  = (STAGE == 1) ? 0 : 2 * FD;
    const float* h = (STAGE == 1) ? g_h1 : g_h2;
    int g = blockIdx.y;
    int t = threadIdx.x;

    __shared__ float ssc[K];
    __shared__ int   ssi[K];
    for (int i = t; i < K; i += 256) { ssc[i] = g_sc[g * 256 + i]; ssi[i] = g_si[g * 256 + i]; }
    __syncthreads();

    if (blockIdx.x < 6) {
        int c  = blockIdx.x * 64 + (t & 63);
        int rg = t >> 6;                              // 0..3
        float mx = -FLT_MAX, sm = 0.f;
        if (c < FD) {
#pragma unroll 4
            for (int r = rg; r < K; r += 4) {
                float v = h[(size_t)(g * n_per + ssi[r]) * FD + c] * ssc[r];
                mx = fmaxf(mx, v); sm += v;
            }
        }
        __shared__ float smax[256], ssum[256];
        smax[t] = mx; ssum[t] = sm;
        __syncthreads();
        if (rg == 0 && c < FD) {
            float M0 = fmaxf(fmaxf(smax[t], smax[t+64]), fmaxf(smax[t+128], smax[t+192]));
            float S0 = ssum[t] + ssum[t+64] + ssum[t+128] + ssum[t+192];
            g_z[g * ZDIM + zoff + c]      = M0;
            g_z[g * ZDIM + zoff + FD + c] = S0 / (float)K;
        }
    } else if (STAGE == 1) {
        int bb = blockIdx.x - 6;
        int r0 = bb * 28, r1 = min(K, r0 + 28);
        for (int r = r0; r < r1; r++) {
            const float* hr = &h[(size_t)(g * n_per + ssi[r]) * FD];
            float s = ssc[r];
            float* orow = &g_hp1[(size_t)(g * K + r) * FD];
            for (int i = t; i < FD; i += 256) orow[i] = hr[i] * s;
        }
    }
}

// ======== fused MLP head (single block) =================================
__global__ void k_head(const float* __restrict__ fc1W, const float* __restrict__ fc1b,
                       const float* __restrict__ bn1g, const float* __restrict__ bn1b,
                       const float* __restrict__ fc2W, const float* __restrict__ fc2b,
                       const float* __restrict__ bn2g, const float* __restrict__ bn2b,
                       const float* __restrict__ fc3W, const float* __restrict__ fc3b,
                       float* __restrict__ out)
{
    int t = threadIdx.x;                 // 352
    __shared__ float sz[2 * ZDIM];
    __shared__ float s1[2 * FD];
    __shared__ float s2[2 * DD3];
    for (int i = t; i < 2 * ZDIM; i += 352) sz[i] = g_z[i];
    __syncthreads();

    if (t < FD) {
        float a0 = 0.f, a1 = 0.f;
        for (int i = 0; i < ZDIM; i++) {
            float wv = fc1W[(size_t)i * FD + t];
            a0 += sz[i] * wv;
            a1 += sz[ZDIM + i] * wv;
        }
        a0 += fc1b[t]; a1 += fc1b[t];
        float mn = 0.5f * (a0 + a1);
        float v  = 0.5f * ((a0 - mn)*(a0 - mn) + (a1 - mn)*(a1 - mn));
        float is = rsqrtf(v + 1e-5f);
        s1[t]      = fmaxf((a0 - mn) * is * bn1g[t] + bn1b[t], 0.f);
        s1[FD + t] = fmaxf((a1 - mn) * is * bn1g[t] + bn1b[t], 0.f);
    }
    __syncthreads();
    if (t < DD3) {
        float a0 = 0.f, a1 = 0.f;
        for (int i = 0; i < FD; i++) {
            float wv = fc2W[(size_t)i * DD3 + t];
            a0 += s1[i] * wv;
            a1 += s1[FD + i] * wv;
        }
        a0 += fc2b[t]; a1 += fc2b[t];
        float mn = 0.5f * (a0 + a1);
        float v  = 0.5f * ((a0 - mn)*(a0 - mn) + (a1 - mn)*(a1 - mn));
        float is = rsqrtf(v + 1e-5f);
        s2[t]       = fmaxf((a0 - mn) * is * bn2g[t] + bn2b[t], 0.f);
        s2[DD3 + t] = fmaxf((a1 - mn) * is * bn2g[t] + bn2b[t], 0.f);
    }
    __syncthreads();
    if (t < 2) {
        float a0 = 0.f, a1 = 0.f;
        for (int i = 0; i < DD3; i++) {
            float wv = fc3W[i*2 + t];
            a0 += s2[i] * wv;
            a1 += s2[DD3 + i] * wv;
        }
        out[t]     = a0 + fc3b[t];
        out[2 + t] = a1 + fc3b[t];
    }
}

// ---------------- launch -------------------------------------------------
extern "C" void kernel_launch(void* const* d_in, const int* in_sizes, int n_in,
                              void* d_out, int out_size)
{
    const float* x     = (const float*)d_in[0];
    const int*   ei    = (const int*)  d_in[1];
    const float* eattr = (const float*)d_in[3];
    const float* c1W1  = (const float*)d_in[6];
    const float* c1W2  = (const float*)d_in[7];
    const float* c1nb  = (const float*)d_in[8];
    const float* c1b   = (const float*)d_in[9];
    const float* p1w   = (const float*)d_in[10];
    const float* c2W1  = (const float*)d_in[11];
    const float* c2W2  = (const float*)d_in[12];
    const float* c2nb  = (const float*)d_in[13];
    const float* c2b   = (const float*)d_in[14];
    const float* p2w   = (const float*)d_in[15];
    const float* fc1W  = (const float*)d_in[16];
    const float* fc1b  = (const float*)d_in[17];
    const float* bn1g  = (const float*)d_in[18];
    const float* bn1b  = (const float*)d_in[19];
    const float* fc2W  = (const float*)d_in[20];
    const float* fc2b  = (const float*)d_in[21];
    const float* bn2g  = (const float*)d_in[22];
    const float* bn2b  = (const float*)d_in[23];
    const float* fc3W  = (const float*)d_in[24];
    const float* fc3b  = (const float*)d_in[25];
    float* out = (float*)d_out;

    // conv1 (GEMM + fused CSR + fused reduce)
    k_gemm<0><<<dim3(6, (NN + BM - 1) / BM, KSPL + 1), 128>>>(x, c1W1, c1W2, c1nb, ei, p1w);
    k_agg<<<dim3(NN, 2), 128>>>(0, eattr, c1b, p1w);
    // pool1
    k_sort<1><<<Gg, 512>>>();
    k_post<1><<<dim3(12, Gg), 256>>>();
    // conv2 (GEMM + fused CSR + fused reduce)
    k_gemm<1><<<dim3(6, (Gg*KP1 + BM - 1) / BM, KSPL + 1), 128>>>(x, c2W1, c2W2, c2nb, ei, p2w);
    k_agg<<<dim3(Gg*KP1, 2), 128>>>(1, eattr, c2b, p2w);
    // pool2
    k_sort<2><<<Gg, 512>>>();
    k_post<2><<<dim3(6, Gg), 256>>>();
    // head
    k_head<<<1, 352>>>(fc1W, fc1b, bn1g, bn1b, fc2W, fc2b, bn2g, bn2b, fc3W, fc3b, out);
}

// round 15
// speedup vs baseline: 1.3553x; 1.3553x over previous
#include <cuda_runtime.h>
#include <math.h>
#include <float.h>

// ---------------- problem constants ----------------
#define Gg    2
#define NPn   332
#define NN    664
#define NE    21248
#define FD    332
#define KD    2324          // 7*FD : 6 W2 slices + nb channel
#define W2SZ  (FD*FD)
#define KP1   166
#define KP2   83
#define ZDIM  1328
#define DD3   128
#define BM    64
#define BN    64
#define BK    16

// ---------------- packed fp32x2 helpers ----------------
#define FMA2(acc, a2, b2) asm("fma.rn.f32x2 %0, %1, %2, %0;" : "+l"(acc) : "l"(a2), "l"(b2))
#define PACK2(d, f)       asm("mov.b64 %0, {%1, %1};" : "=l"(d) : "r"(__float_as_uint(f)))
#define UNPACK2(lo, hi, v) asm("mov.b64 {%0, %1}, %2;" : "=r"(lo), "=r"(hi) : "l"(v))

// ---------------- scratch ----------------
__device__ __align__(16) float g_part[16 * NN * FD]; // split-K partials
__device__ __align__(16) float g_xt [NN * FD];
__device__ __align__(16) float g_h1 [NN * FD];
__device__ __align__(16) float g_h2 [NN * FD];
__device__ float g_dp [2 * NN];        // per-half TopK dot partials
__device__ float g_sc [Gg * 256];
__device__ int   g_si [Gg * 256];
__device__ int   g_perm1 [Gg*KP1];
__device__ int   g_newidx1[NN];
__device__ int   g_cnt[NN];            // zeroed at end of every call (and at load)
__device__ int   g_csr_ptr[NN + 1];
__device__ int   g_csr_eid[NE];
__device__ int   g_csr_src[NE];
__device__ float g_invn[2];
__device__ float g_z  [Gg * ZDIM];

// ======== CSR: count (wide) =============================================
template<int STAGE>
__global__ void k_count(const int* __restrict__ ei)
{
    int e = blockIdx.x * 256 + threadIdx.x;
    if (e >= NE) return;
    int d = ei[NE + e];
    if (STAGE) {
        int ns = g_newidx1[ei[e]];
        int nd = g_newidx1[d];
        if (ns < 0 || nd < 0) return;
        d = nd;
    }
    atomicAdd(&g_cnt[d], 1);
}

// ======== CSR: scan (1 block) + pw norm =================================
template<int STAGE>
__global__ void k_scan(const float* __restrict__ pw)
{
    constexpr int n_dst = STAGE ? (Gg * KP1) : NN;
    __shared__ int   cnt[1024];
    __shared__ float sred[1024];
    int t = threadIdx.x;
    cnt[t] = (t < n_dst) ? g_cnt[t] : 0;
    float p = 0.f;
    for (int i = t; i < FD; i += 1024) p += pw[i] * pw[i];
    sred[t] = p;
    __syncthreads();
    for (int off = 1; off < 1024; off <<= 1) {
        int v = (t >= off) ? cnt[t - off] : 0;
        __syncthreads();
        cnt[t] += v;
        __syncthreads();
    }
    for (int s = 512; s; s >>= 1) { if (t < s) sred[t] += sred[t + s]; __syncthreads(); }
    if (t == 0) { g_invn[STAGE] = rsqrtf(sred[0]); g_csr_ptr[0] = 0; }
    if (t < n_dst) { g_csr_ptr[t + 1] = cnt[t]; g_cnt[t] = 0; }
}

// ======== CSR: fill (wide) ==============================================
template<int STAGE>
__global__ void k_fill(const int* __restrict__ ei)
{
    int e = blockIdx.x * 256 + threadIdx.x;
    if (e >= NE) return;
    int s = ei[e], d = ei[NE + e];
    if (STAGE) {
        s = g_newidx1[s];
        int nd = g_newidx1[d];
        if (s < 0 || nd < 0) return;
        d = nd;
    }
    int slot = atomicAdd(&g_cnt[d], 1);
    int p = g_csr_ptr[d] + slot;
    g_csr_eid[p] = e;
    g_csr_src[p] = s;
}

// ======== conv GEMM: 64x64 tile, 8x4/thread, FFMA2, split-K =============
// partial[z][M,332] = A_z[M,*]@B_z ; A[m,kk*332+ki] = X[m,ki]*h6[m,kk]
// STAGE 0: X = x, h6[m,:] = relu(W1[m%332,:]) (+1 nb channel).
// STAGE 1: X row m = g_h1[perm1[m]], h6 scaled by pooled score sc[m]
//          (folds the hp1 = h1[perm]*score materialization into the GEMM).
template<int STAGE, int KS>
__global__ void __launch_bounds__(128, 8) k_gemm(const float* __restrict__ Xin,
        const float* __restrict__ W1, const float* __restrict__ W2,
        const float* __restrict__ nb)
{
    constexpr int M = STAGE ? (Gg * KP1) : NN;
    const float* X = STAGE ? (const float*)g_h1 : Xin;
    __shared__ __align__(16) float As[2][BK][BM + 4];   // pitch 272B
    __shared__ __align__(16) float Bs[2][BK][BN + 4];
    __shared__ float h6s[BM][9];                        // pitch 9: lane reads conflict-free
    const int tid  = threadIdx.x;
    const int tx   = tid & 15, ty = tid >> 4;           // 16 x 8
    const int lane = tid & 31, w  = tid >> 5;
    const int row0 = blockIdx.y * BM, col0 = blockIdx.x * BN;

    for (int l = tid; l < BM * 8; l += 128) {
        int m = l >> 3, k = l & 7;
        int r = row0 + m; if (r >= M) r = M - 1;
        float v = 0.f;
        if (STAGE == 0) {
            if (k == 6) v = 1.f;
            else if (k < 6) v = fmaxf(W1[(r % NPn) * 6 + k], 0.f);
        } else {
            int gg  = r / KP1;
            float sc = g_sc[gg * 256 + (r - gg * KP1)];
            if (k == 6) v = sc;
            else if (k < 6) {
                int rid = g_perm1[r] % NPn;
                v = fmaxf(W1[rid * 6 + k], 0.f) * sc;
            }
        }
        h6s[m][k] = v;
    }
    __syncthreads();

    const int  rA0 = row0 + lane, rA1 = row0 + lane + 32;
    const bool ok0 = (rA0 < M), ok1 = (rA1 < M);
    const int  srcA0 = STAGE ? g_perm1[ok0 ? rA0 : 0] : rA0;
    const int  srcA1 = STAGE ? g_perm1[ok1 ? rA1 : 0] : rA1;

    constexpr int NCH = (KD + BK - 1) / BK;        // 146
    const int z    = blockIdx.z;
    const int cbeg = (NCH * z) / KS;
    const int cend = (NCH * (z + 1)) / KS;

    const int kB = tid >> 3, nB = (tid & 7) << 3;

    auto load_tile = [&](int c, int buf) {
        // ---- A tile (64 x 16): warp w owns k-rows {4w..4w+3} ----
        int kg0 = c * BK + 4 * w;
        float4 x0 = make_float4(0.f,0.f,0.f,0.f), x1 = x0;
        float  h0 = 0.f, h1 = 0.f;
        if (kg0 < KD) {
            int kk  = kg0 / FD;
            int ki0 = kg0 - kk * FD;
            if (ok0) x0 = *(const float4*)(X + (size_t)srcA0 * FD + ki0);
            if (ok1) x1 = *(const float4*)(X + (size_t)srcA1 * FD + ki0);
            h0 = h6s[lane][kk]; h1 = h6s[lane + 32][kk];
        }
        As[buf][4*w + 0][lane]      = x0.x * h0;
        As[buf][4*w + 1][lane]      = x0.y * h0;
        As[buf][4*w + 2][lane]      = x0.z * h0;
        As[buf][4*w + 3][lane]      = x0.w * h0;
        As[buf][4*w + 0][lane + 32] = x1.x * h1;
        As[buf][4*w + 1][lane + 32] = x1.y * h1;
        As[buf][4*w + 2][lane + 32] = x1.z * h1;
        As[buf][4*w + 3][lane + 32] = x1.w * h1;
        // ---- B tile (16 x 64) ----
        int kg = c * BK + kB;
        float4 v0 = make_float4(0.f,0.f,0.f,0.f), v1 = v0;
        if (kg < KD) {
            int kkb = kg / FD, ki = kg - kkb * FD;
            const float* bp = (kkb < 6) ? (W2 + (size_t)kkb * W2SZ + (size_t)ki * FD)
                                        : (nb + (size_t)ki * FD);
            int cA = col0 + nB;
            if (cA + 3 < FD) v0 = *(const float4*)(bp + cA);
            if (cA + 7 < FD) v1 = *(const float4*)(bp + cA + 4);
        }
        *(float4*)&Bs[buf][kB][nB]     = v0;
        *(float4*)&Bs[buf][kB][nB + 4] = v1;
    };

    unsigned long long acc[8][2] = {};
    load_tile(cbeg, 0);
    __syncthreads();
    for (int c = cbeg; c < cend; c++) {
        int buf = (c - cbeg) & 1;
        if (c + 1 < cend) load_tile(c + 1, buf ^ 1);
#pragma unroll
        for (int kk = 0; kk < BK; kk++) {
            ulonglong2 bv = *(const ulonglong2*)&Bs[buf][kk][tx << 2];
            float4 a0 = *(const float4*)&As[buf][kk][ty << 3];       // broadcast
            float4 a1 = *(const float4*)&As[buf][kk][(ty << 3) + 4];
            unsigned long long p0,p1,p2,p3,p4,p5,p6,p7;
            PACK2(p0, a0.x); PACK2(p1, a0.y); PACK2(p2, a0.z); PACK2(p3, a0.w);
            PACK2(p4, a1.x); PACK2(p5, a1.y); PACK2(p6, a1.z); PACK2(p7, a1.w);
            FMA2(acc[0][0], p0, bv.x); FMA2(acc[0][1], p0, bv.y);
            FMA2(acc[1][0], p1, bv.x); FMA2(acc[1][1], p1, bv.y);
            FMA2(acc[2][0], p2, bv.x); FMA2(acc[2][1], p2, bv.y);
            FMA2(acc[3][0], p3, bv.x); FMA2(acc[3][1], p3, bv.y);
            FMA2(acc[4][0], p4, bv.x); FMA2(acc[4][1], p4, bv.y);
            FMA2(acc[5][0], p5, bv.x); FMA2(acc[5][1], p5, bv.y);
            FMA2(acc[6][0], p6, bv.x); FMA2(acc[6][1], p6, bv.y);
            FMA2(acc[7][0], p7, bv.x); FMA2(acc[7][1], p7, bv.y);
        }
        __syncthreads();
    }

    int cc = col0 + (tx << 2);
    if (cc + 3 < FD) {
        float* base = &g_part[(size_t)z * M * FD];
#pragma unroll
        for (int j = 0; j < 8; j++) {
            int r = row0 + (ty << 3) + j;
            if (r < M) {
                unsigned int x0,x1,x2,x3;
                UNPACK2(x0, x1, acc[j][0]);
                UNPACK2(x2, x3, acc[j][1]);
                *(float4*)&base[(size_t)r * FD + cc] = make_float4(
                    __uint_as_float(x0), __uint_as_float(x1),
                    __uint_as_float(x2), __uint_as_float(x3));
            }
        }
    }
}

// ======== split-K reduce (fixed order => deterministic) =================
template<int M, int KS>
__global__ void k_reduce()
{
    constexpr int total = M * FD / 4;
    int i = blockIdx.x * 256 + threadIdx.x;
    if (i >= total) return;
    const float4* p = (const float4*)g_part;
    float4 s = p[i];
#pragma unroll
    for (int z = 1; z < KS; z++) {
        float4 v = p[(size_t)z * total + i];
        s.x += v.x; s.y += v.y; s.z += v.z; s.w += v.w;
    }
    ((float4*)g_xt)[i] = s;
}

// ======== softmax aggregation (col-split) + TopK dot partial ============
// grid (n_dst, 2); block handles cols [half*166, half*166+166)
__global__ void k_agg(int outsel, const float* __restrict__ eattr,
                      const float* __restrict__ bias, const float* __restrict__ pw)
{
    int d    = blockIdx.x;
    int half = blockIdx.y;
    int t = threadIdx.x;                 // 128
    __shared__ float sred[128];
    __shared__ float ws[128];
    __shared__ int   ss[128];

    int begin = g_csr_ptr[d], end = g_csr_ptr[d + 1];
    int deg = end - begin;

    float m = 1.0f;                      // self-loop logit
    for (int e = begin + t; e < end; e += 128) m = fmaxf(m, eattr[g_csr_eid[e]]);
    sred[t] = m; __syncthreads();
    for (int s = 64; s; s >>= 1) { if (t < s) sred[t] = fmaxf(sred[t], sred[t + s]); __syncthreads(); }
    m = sred[0]; __syncthreads();

    float se = 0.f;
    for (int e = begin + t; e < end; e += 128) se += expf(eattr[g_csr_eid[e]] - m);
    sred[t] = se; __syncthreads();
    for (int s = 64; s; s >>= 1) { if (t < s) sred[t] += sred[t + s]; __syncthreads(); }
    float selfe = expf(1.0f - m);
    float inv = 1.f / (sred[0] + selfe);
    float selfw = selfe * inv;
    __syncthreads();

    const int base = half * 166;
    const int o0 = base + t;             // always < 332
    const int o1 = base + 128 + t;       // valid for t < 38
    const bool has1 = (t < 38);
    const float* xd = &g_xt[(size_t)d * FD];
    float acc0 = selfw * xd[o0];
    float acc1 = has1 ? selfw * xd[o1] : 0.f;

    for (int c0 = 0; c0 < deg; c0 += 128) {
        if (c0 + t < deg) {
            int e = begin + c0 + t;
            ws[t] = expf(eattr[g_csr_eid[e]] - m) * inv;
            ss[t] = g_csr_src[e];
        }
        __syncthreads();
        int cn = min(128, deg - c0);
        int q = 0;
        for (; q + 4 <= cn; q += 4) {
            const float* x0 = &g_xt[(size_t)ss[q]   * FD];
            const float* x1 = &g_xt[(size_t)ss[q+1] * FD];
            const float* x2 = &g_xt[(size_t)ss[q+2] * FD];
            const float* x3 = &g_xt[(size_t)ss[q+3] * FD];
            float w0 = ws[q], w1 = ws[q+1], w2 = ws[q+2], w3 = ws[q+3];
            acc0 += w0*x0[o0] + w1*x1[o0] + w2*x2[o0] + w3*x3[o0];
            if (has1) acc1 += w0*x0[o1] + w1*x1[o1] + w2*x2[o1] + w3*x3[o1];
        }
        for (; q < cn; q++) {
            float wv = ws[q];
            const float* xr = &g_xt[(size_t)ss[q] * FD];
            acc0 += wv * xr[o0];
            if (has1) acc1 += wv * xr[o1];
        }
        __syncthreads();
    }
    acc0 += bias[o0];
    if (has1) acc1 += bias[o1];
    float* out = outsel ? g_h2 : g_h1;
    out[(size_t)d * FD + o0] = acc0;
    if (has1) out[(size_t)d * FD + o1] = acc1;

    // partial TopK dot for this column half
    float dp = acc0 * pw[o0] + (has1 ? acc1 * pw[o1] : 0.f);
    sred[t] = dp; __syncthreads();
    for (int s = 64; s; s >>= 1) { if (t < s) sred[t] += sred[t + s]; __syncthreads(); }
    if (t == 0) g_dp[half * NN + d] = sred[0];
}

// ======== sort: combine dot partials -> score -> bitonic ================
template<int STAGE>
__global__ void k_sort()
{
    constexpr int n_per = (STAGE == 1) ? NPn : KP1;
    constexpr int K     = (STAGE == 1) ? KP1 : KP2;
    int g = blockIdx.x;
    int t = threadIdx.x;                 // 512
    __shared__ float sc[512];
    __shared__ int   si[512];
    float invn = g_invn[STAGE - 1];
    if (t < n_per) {
        int node = g * n_per + t;
        float dp = g_dp[node] + g_dp[NN + node];
        sc[t] = 1.f / (1.f + expf(-dp * invn));
        si[t] = t;
    } else { sc[t] = -FLT_MAX; si[t] = 100000 + t; }
    if (STAGE == 1 && t < NPn) g_cnt[g * NPn + t] = 0;   // reset counters for stage 2
    __syncthreads();

    for (int k = 2; k <= 512; k <<= 1) {
        for (int j = k >> 1; j; j >>= 1) {
            int ixj = t ^ j;
            if (ixj > t) {
                float a = sc[t], b2 = sc[ixj];
                int ia = si[t], ib = si[ixj];
                bool afirst = (a > b2) || (a == b2 && ia < ib);
                bool up = ((t & k) == 0);
                if (up ? !afirst : afirst) { sc[t] = b2; sc[ixj] = a; si[t] = ib; si[ixj] = ia; }
            }
            __syncthreads();
        }
    }
    if (t < K) { g_si[g * 256 + t] = si[t]; g_sc[g * 256 + t] = sc[t]; }
    if (STAGE == 1) {
        if (t < n_per) g_newidx1[g * n_per + t] = -1;
        __syncthreads();
        if (t < K) {
            g_newidx1[g * n_per + si[t]] = g * K + t;
            g_perm1[g * K + t] = g * n_per + si[t];
        }
    }
}

// ======== wide-grid post: readout only (512 thr, 8 row-groups) ==========
template<int STAGE>
__global__ void __launch_bounds__(512) k_post()
{
    constexpr int n_per = (STAGE == 1) ? NPn : KP1;
    constexpr int K     = (STAGE == 1) ? KP1 : KP2;
    constexpr int zoff  = (STAGE == 1) ? 0 : 2 * FD;
    const float* h = (STAGE == 1) ? g_h1 : g_h2;
    int g = blockIdx.y;
    int t = threadIdx.x;

    __shared__ float ssc[K];
    __shared__ int   ssi[K];
    for (int i = t; i < K; i += 512) { ssc[i] = g_sc[g * 256 + i]; ssi[i] = g_si[g * 256 + i]; }
    __syncthreads();

    int c  = blockIdx.x * 64 + (t & 63);
    int rg = t >> 6;                              // 0..7
    float mx = -FLT_MAX, sm = 0.f;
    if (c < FD) {
#pragma unroll 4
        for (int r = rg; r < K; r += 8) {
            float v = h[(size_t)(g * n_per + ssi[r]) * FD + c] * ssc[r];
            mx = fmaxf(mx, v); sm += v;
        }
    }
    __shared__ float smax[512], ssum[512];
    smax[t] = mx; ssum[t] = sm;
    __syncthreads();
    if (rg == 0 && c < FD) {
        float M0 = mx, S0 = sm;
#pragma unroll
        for (int q = 1; q < 8; q++) {
            M0 = fmaxf(M0, smax[t + q * 64]);
            S0 += ssum[t + q * 64];
        }
        g_z[g * ZDIM + zoff + c]      = M0;
        g_z[g * ZDIM + zoff + FD + c] = S0 / (float)K;
    }
}

// ======== fused MLP head (single block) + cleanup =======================
__global__ void k_head(const float* __restrict__ fc1W, const float* __restrict__ fc1b,
                       const float* __restrict__ bn1g, const float* __restrict__ bn1b,
                       const float* __restrict__ fc2W, const float* __restrict__ fc2b,
                       const float* __restrict__ bn2g, const float* __restrict__ bn2b,
                       const float* __restrict__ fc3W, const float* __restrict__ fc3b,
                       float* __restrict__ out)
{
    int t = threadIdx.x;                 // 352
    __shared__ float sz[2 * ZDIM];
    __shared__ float s1[2 * FD];
    __shared__ float s2[2 * DD3];
    for (int i = t; i < 2 * ZDIM; i += 352) sz[i] = g_z[i];
    for (int i = t; i < NN; i += 352) g_cnt[i] = 0;   // reset for next replay
    __syncthreads();

    if (t < FD) {
        float a0 = 0.f, a1 = 0.f;
        for (int i = 0; i < ZDIM; i++) {
            float wv = fc1W[(size_t)i * FD + t];
            a0 += sz[i] * wv;
            a1 += sz[ZDIM + i] * wv;
        }
        a0 += fc1b[t]; a1 += fc1b[t];
        float mn = 0.5f * (a0 + a1);
        float v  = 0.5f * ((a0 - mn)*(a0 - mn) + (a1 - mn)*(a1 - mn));
        float is = rsqrtf(v + 1e-5f);
        s1[t]      = fmaxf((a0 - mn) * is * bn1g[t] + bn1b[t], 0.f);
        s1[FD + t] = fmaxf((a1 - mn) * is * bn1g[t] + bn1b[t], 0.f);
    }
    __syncthreads();
    if (t < DD3) {
        float a0 = 0.f, a1 = 0.f;
        for (int i = 0; i < FD; i++) {
            float wv = fc2W[(size_t)i * DD3 + t];
            a0 += s1[i] * wv;
            a1 += s1[FD + i] * wv;
        }
        a0 += fc2b[t]; a1 += fc2b[t];
        float mn = 0.5f * (a0 + a1);
        float v  = 0.5f * ((a0 - mn)*(a0 - mn) + (a1 - mn)*(a1 - mn));
        float is = rsqrtf(v + 1e-5f);
        s2[t]       = fmaxf((a0 - mn) * is * bn2g[t] + bn2b[t], 0.f);
        s2[DD3 + t] = fmaxf((a1 - mn) * is * bn2g[t] + bn2b[t], 0.f);
    }
    __syncthreads();
    if (t < 2) {
        float a0 = 0.f, a1 = 0.f;
        for (int i = 0; i < DD3; i++) {
            float wv = fc3W[i*2 + t];
            a0 += s2[i] * wv;
            a1 += s2[DD3 + i] * wv;
        }
        out[t]     = a0 + fc3b[t];
        out[2 + t] = a1 + fc3b[t];
    }
}

// ---------------- launch -------------------------------------------------
extern "C" void kernel_launch(void* const* d_in, const int* in_sizes, int n_in,
                              void* d_out, int out_size)
{
    const float* x     = (const float*)d_in[0];
    const int*   ei    = (const int*)  d_in[1];
    const float* eattr = (const float*)d_in[3];
    const float* c1W1  = (const float*)d_in[6];
    const float* c1W2  = (const float*)d_in[7];
    const float* c1nb  = (const float*)d_in[8];
    const float* c1b   = (const float*)d_in[9];
    const float* p1w   = (const float*)d_in[10];
    const float* c2W1  = (const float*)d_in[11];
    const float* c2W2  = (const float*)d_in[12];
    const float* c2nb  = (const float*)d_in[13];
    const float* c2b   = (const float*)d_in[14];
    const float* p2w   = (const float*)d_in[15];
    const float* fc1W  = (const float*)d_in[16];
    const float* fc1b  = (const float*)d_in[17];
    const float* bn1g  = (const float*)d_in[18];
    const float* bn1b  = (const float*)d_in[19];
    const float* fc2W  = (const float*)d_in[20];
    const float* fc2b  = (const float*)d_in[21];
    const float* bn2g  = (const float*)d_in[22];
    const float* bn2b  = (const float*)d_in[23];
    const float* fc3W  = (const float*)d_in[24];
    const float* fc3b  = (const float*)d_in[25];
    float* out = (float*)d_out;

    // conv1
    k_count<0><<<NE/256, 256>>>(ei);
    k_scan <0><<<1, 1024>>>(p1w);
    k_fill <0><<<NE/256, 256>>>(ei);
    k_gemm<0,16><<<dim3(6, (NN + BM - 1) / BM, 16), 128>>>(x, c1W1, c1W2, c1nb);
    k_reduce<NN, 16><<<(NN*FD/4 + 255)/256, 256>>>();
    k_agg<<<dim3(NN, 2), 128>>>(0, eattr, c1b, p1w);
    // pool1
    k_sort<1><<<Gg, 512>>>();
    k_post<1><<<dim3(6, Gg), 512>>>();
    // conv2 (reads g_h1 via perm, score folded into h6)
    k_count<1><<<NE/256, 256>>>(ei);
    k_scan <1><<<1, 1024>>>(p2w);
    k_fill <1><<<NE/256, 256>>>(ei);
    k_gemm<1,16><<<dim3(6, (Gg*KP1 + BM - 1) / BM, 16), 128>>>(x, c2W1, c2W2, c2nb);
    k_reduce<Gg*KP1, 16><<<(Gg*KP1*FD/4 + 255)/256, 256>>>();
    k_agg<<<dim3(Gg*KP1, 2), 128>>>(1, eattr, c2b, p2w);
    // pool2
    k_sort<2><<<Gg, 512>>>();
    k_post<2><<<dim3(6, Gg), 512>>>();
    // head
    k_head<<<1, 352>>>(fc1W, fc1b, bn1g, bn1b, fc2W, fc2b, bn2g, bn2b, fc3W, fc3b, out);
}

// round 17
// speedup vs baseline: 1.4134x; 1.0429x over previous
#include <cuda_runtime.h>
#include <math.h>
#include <float.h>

// ---------------- problem constants ----------------
#define Gg    2
#define NPn   332
#define NN    664
#define NE    21248
#define FD    332
#define KD    2324          // 7*FD : 6 W2 slices + nb channel
#define W2SZ  (FD*FD)
#define KP1   166
#define KP2   83
#define ZDIM  1328
#define DD3   128
#define BM    64
#define BN    64
#define BK    16
#define KSPL  16

// ---------------- packed fp32x2 helpers ----------------
#define FMA2(acc, a2, b2) asm("fma.rn.f32x2 %0, %1, %2, %0;" : "+l"(acc) : "l"(a2), "l"(b2))
#define PACK2(d, f)       asm("mov.b64 %0, {%1, %1};" : "=l"(d) : "r"(__float_as_uint(f)))
#define UNPACK2(lo, hi, v) asm("mov.b64 {%0, %1}, %2;" : "=r"(lo), "=r"(hi) : "l"(v))

// ---------------- scratch ----------------
__device__ __align__(16) float g_part[KSPL * NN * FD]; // split-K partials
__device__ __align__(16) float g_xt [NN * FD];
__device__ __align__(16) float g_h1 [NN * FD];
__device__ __align__(16) float g_h2 [NN * FD];
__device__ float g_dp [2 * NN];        // per-half TopK dot partials
__device__ float g_sc [Gg * 256];
__device__ int   g_si [Gg * 256];
__device__ int   g_perm1 [Gg*KP1];
__device__ int   g_newidx1[NN];
__device__ int   g_cnt[NN];            // zeroed at end of every call (and at load)
__device__ int   g_csr_ptr[NN + 1];
__device__ int   g_csr_eid[NE];
__device__ int   g_csr_src[NE];
__device__ float g_invn[2];
__device__ float g_z  [Gg * ZDIM];

// ======== CSR: count (wide, stage 0 standalone) =========================
__global__ void k_count0(const int* __restrict__ ei)
{
    int e = blockIdx.x * 256 + threadIdx.x;
    if (e >= NE) return;
    atomicAdd(&g_cnt[ei[NE + e]], 1);
}

// ======== conv GEMM: 64x64 tile, 8x4/thread, FFMA2, split-K =============
// z == KSPL: single scan block (exclusive-scan g_cnt -> g_csr_ptr, pw norm,
//            zero g_cnt). Independent of the GEMM blocks; hides under them.
// STAGE 0: X = x, h6[m,:] = relu(W1[m%332,:]) (+1 nb channel).
// STAGE 1: X row m = g_h1[perm1[m]], h6 scaled by pooled score sc[m].
template<int STAGE>
__global__ void __launch_bounds__(128, 8) k_gemm(const float* __restrict__ Xin,
        const float* __restrict__ W1, const float* __restrict__ W2,
        const float* __restrict__ nb, const float* __restrict__ pw)
{
    constexpr int M = STAGE ? (Gg * KP1) : NN;
    const int tid = threadIdx.x;

    if (blockIdx.z == KSPL) {            // ---- fused scan block ----
        if (blockIdx.x != 0 || blockIdx.y != 0) return;
        constexpr int NDST = M;
        constexpr int PER  = (NDST + 127) / 128;
        __shared__ int   cnt[NDST];
        __shared__ float red[128];
        __shared__ int   wsum[128];
        float p = 0.f;
        for (int i = tid; i < FD; i += 128) p += pw[i] * pw[i];
        red[tid] = p; __syncthreads();
        for (int s = 64; s; s >>= 1) { if (tid < s) red[tid] += red[tid + s]; __syncthreads(); }
        if (tid == 0) g_invn[STAGE] = rsqrtf(red[0]);
        for (int i = tid; i < NDST; i += 128) cnt[i] = g_cnt[i];
        __syncthreads();
        int base = tid * PER, loc = 0;
#pragma unroll
        for (int j = 0; j < PER; j++) {
            int idx = base + j;
            if (idx < NDST) { int v = cnt[idx]; cnt[idx] = loc; loc += v; }
        }
        wsum[tid] = loc; __syncthreads();
        for (int off = 1; off < 128; off <<= 1) {
            int v = (tid >= off) ? wsum[tid - off] : 0;
            __syncthreads();
            wsum[tid] += v;
            __syncthreads();
        }
        int add = tid ? wsum[tid - 1] : 0;
#pragma unroll
        for (int j = 0; j < PER; j++) {
            int idx = base + j;
            if (idx < NDST) cnt[idx] += add;
        }
        __syncthreads();
        for (int i = tid; i < NDST; i += 128) { g_csr_ptr[i] = cnt[i]; g_cnt[i] = 0; }
        if (tid == 0) g_csr_ptr[NDST] = wsum[127];
        return;
    }

    // ---- GEMM path ----
    const float* X = STAGE ? (const float*)g_h1 : Xin;
    __shared__ __align__(16) float As[2][BK][BM + 4];   // pitch 272B
    __shared__ __align__(16) float Bs[2][BK][BN + 4];
    __shared__ float h6s[BM][9];                        // pitch 9: lane reads conflict-free
    const int tx   = tid & 15, ty = tid >> 4;           // 16 x 8
    const int lane = tid & 31, w  = tid >> 5;
    const int row0 = blockIdx.y * BM, col0 = blockIdx.x * BN;

    for (int l = tid; l < BM * 8; l += 128) {
        int m = l >> 3, k = l & 7;
        int r = row0 + m; if (r >= M) r = M - 1;
        float v = 0.f;
        if (STAGE == 0) {
            if (k == 6) v = 1.f;
            else if (k < 6) v = fmaxf(W1[(r % NPn) * 6 + k], 0.f);
        } else {
            int gg  = r / KP1;
            float sc = g_sc[gg * 256 + (r - gg * KP1)];
            if (k == 6) v = sc;
            else if (k < 6) {
                int rid = g_perm1[r] % NPn;
                v = fmaxf(W1[rid * 6 + k], 0.f) * sc;
            }
        }
        h6s[m][k] = v;
    }
    __syncthreads();

    const int  rA0 = row0 + lane, rA1 = row0 + lane + 32;
    const bool ok0 = (rA0 < M), ok1 = (rA1 < M);
    const int  srcA0 = STAGE ? g_perm1[ok0 ? rA0 : 0] : rA0;
    const int  srcA1 = STAGE ? g_perm1[ok1 ? rA1 : 0] : rA1;

    constexpr int NCH = (KD + BK - 1) / BK;        // 146
    const int z    = blockIdx.z;
    const int cbeg = (NCH * z) / KSPL;
    const int cend = (NCH * (z + 1)) / KSPL;

    const int kB = tid >> 3, nB = (tid & 7) << 3;

    auto load_tile = [&](int c, int buf) {
        // ---- A tile (64 x 16): warp w owns k-rows {4w..4w+3} ----
        int kg0 = c * BK + 4 * w;
        float4 x0 = make_float4(0.f,0.f,0.f,0.f), x1 = x0;
        float  h0 = 0.f, h1 = 0.f;
        if (kg0 < KD) {
            int kk  = kg0 / FD;
            int ki0 = kg0 - kk * FD;
            if (ok0) x0 = *(const float4*)(X + (size_t)srcA0 * FD + ki0);
            if (ok1) x1 = *(const float4*)(X + (size_t)srcA1 * FD + ki0);
            h0 = h6s[lane][kk]; h1 = h6s[lane + 32][kk];
        }
        As[buf][4*w + 0][lane]      = x0.x * h0;
        As[buf][4*w + 1][lane]      = x0.y * h0;
        As[buf][4*w + 2][lane]      = x0.z * h0;
        As[buf][4*w + 3][lane]      = x0.w * h0;
        As[buf][4*w + 0][lane + 32] = x1.x * h1;
        As[buf][4*w + 1][lane + 32] = x1.y * h1;
        As[buf][4*w + 2][lane + 32] = x1.z * h1;
        As[buf][4*w + 3][lane + 32] = x1.w * h1;
        // ---- B tile (16 x 64) ----
        int kg = c * BK + kB;
        float4 v0 = make_float4(0.f,0.f,0.f,0.f), v1 = v0;
        if (kg < KD) {
            int kkb = kg / FD, ki = kg - kkb * FD;
            const float* bp = (kkb < 6) ? (W2 + (size_t)kkb * W2SZ + (size_t)ki * FD)
                                        : (nb + (size_t)ki * FD);
            int cA = col0 + nB;
            if (cA + 3 < FD) v0 = *(const float4*)(bp + cA);
            if (cA + 7 < FD) v1 = *(const float4*)(bp + cA + 4);
        }
        *(float4*)&Bs[buf][kB][nB]     = v0;
        *(float4*)&Bs[buf][kB][nB + 4] = v1;
    };

    unsigned long long acc[8][2] = {};
    load_tile(cbeg, 0);
    __syncthreads();
    for (int c = cbeg; c < cend; c++) {
        int buf = (c - cbeg) & 1;
        if (c + 1 < cend) load_tile(c + 1, buf ^ 1);
#pragma unroll
        for (int kk = 0; kk < BK; kk++) {
            ulonglong2 bv = *(const ulonglong2*)&Bs[buf][kk][tx << 2];
            float4 a0 = *(const float4*)&As[buf][kk][ty << 3];       // broadcast
            float4 a1 = *(const float4*)&As[buf][kk][(ty << 3) + 4];
            unsigned long long p0,p1,p2,p3,p4,p5,p6,p7;
            PACK2(p0, a0.x); PACK2(p1, a0.y); PACK2(p2, a0.z); PACK2(p3, a0.w);
            PACK2(p4, a1.x); PACK2(p5, a1.y); PACK2(p6, a1.z); PACK2(p7, a1.w);
            FMA2(acc[0][0], p0, bv.x); FMA2(acc[0][1], p0, bv.y);
            FMA2(acc[1][0], p1, bv.x); FMA2(acc[1][1], p1, bv.y);
            FMA2(acc[2][0], p2, bv.x); FMA2(acc[2][1], p2, bv.y);
            FMA2(acc[3][0], p3, bv.x); FMA2(acc[3][1], p3, bv.y);
            FMA2(acc[4][0], p4, bv.x); FMA2(acc[4][1], p4, bv.y);
            FMA2(acc[5][0], p5, bv.x); FMA2(acc[5][1], p5, bv.y);
            FMA2(acc[6][0], p6, bv.x); FMA2(acc[6][1], p6, bv.y);
            FMA2(acc[7][0], p7, bv.x); FMA2(acc[7][1], p7, bv.y);
        }
        __syncthreads();
    }

    int cc = col0 + (tx << 2);
    if (cc + 3 < FD) {
        float* base = &g_part[(size_t)z * M * FD];
#pragma unroll
        for (int j = 0; j < 8; j++) {
            int r = row0 + (ty << 3) + j;
            if (r < M) {
                unsigned int x0,x1,x2,x3;
                UNPACK2(x0, x1, acc[j][0]);
                UNPACK2(x2, x3, acc[j][1]);
                *(float4*)&base[(size_t)r * FD + cc] = make_float4(
                    __uint_as_float(x0), __uint_as_float(x1),
                    __uint_as_float(x2), __uint_as_float(x3));
            }
        }
    }
}

// ======== fused: split-K reduce (wide) + CSR fill (wide) ================
// reduce depends on gemm; fill depends on scan — both done in prior launch,
// the two halves are mutually independent.
template<int STAGE>
__global__ void __launch_bounds__(256) k_redfill(const int* __restrict__ ei)
{
    constexpr int M   = STAGE ? (Gg * KP1) : NN;
    constexpr int TOT = M * FD / 4;
    constexpr int RED = (TOT + 255) / 256;
    int bx = blockIdx.x;
    if (bx < RED) {
        int i = bx * 256 + threadIdx.x;
        if (i >= TOT) return;
        const float4* p = (const float4*)g_part;
        float4 s = p[i];
#pragma unroll
        for (int z = 1; z < KSPL; z++) {
            float4 v = p[(size_t)z * TOT + i];
            s.x += v.x; s.y += v.y; s.z += v.z; s.w += v.w;
        }
        ((float4*)g_xt)[i] = s;
    } else {
        int e = (bx - RED) * 256 + threadIdx.x;
        if (e >= NE) return;
        int s = ei[e], d = ei[NE + e];
        if (STAGE) {
            s = g_newidx1[s];
            int nd = g_newidx1[d];
            if (s < 0 || nd < 0) return;
            d = nd;
        }
        int slot = atomicAdd(&g_cnt[d], 1);
        int p = g_csr_ptr[d] + slot;
        g_csr_eid[p] = e;
        g_csr_src[p] = s;
    }
}

// ======== softmax aggregation (col-split) + TopK dot partial ============
__global__ void k_agg(int outsel, const float* __restrict__ eattr,
                      const float* __restrict__ bias, const float* __restrict__ pw)
{
    int d    = blockIdx.x;
    int half = blockIdx.y;
    int t = threadIdx.x;                 // 128
    __shared__ float sred[128];
    __shared__ float ws[128];
    __shared__ int   ss[128];

    int begin = g_csr_ptr[d], end = g_csr_ptr[d + 1];
    int deg = end - begin;

    float m = 1.0f;                      // self-loop logit
    for (int e = begin + t; e < end; e += 128) m = fmaxf(m, eattr[g_csr_eid[e]]);
    sred[t] = m; __syncthreads();
    for (int s = 64; s; s >>= 1) { if (t < s) sred[t] = fmaxf(sred[t], sred[t + s]); __syncthreads(); }
    m = sred[0]; __syncthreads();

    float se = 0.f;
    for (int e = begin + t; e < end; e += 128) se += expf(eattr[g_csr_eid[e]] - m);
    sred[t] = se; __syncthreads();
    for (int s = 64; s; s >>= 1) { if (t < s) sred[t] += sred[t + s]; __syncthreads(); }
    float selfe = expf(1.0f - m);
    float inv = 1.f / (sred[0] + selfe);
    float selfw = selfe * inv;
    __syncthreads();

    const int base = half * 166;
    const int o0 = base + t;             // always < 332
    const int o1 = base + 128 + t;       // valid for t < 38
    const bool has1 = (t < 38);
    const float* xd = &g_xt[(size_t)d * FD];
    float acc0 = selfw * xd[o0];
    float acc1 = has1 ? selfw * xd[o1] : 0.f;

    for (int c0 = 0; c0 < deg; c0 += 128) {
        if (c0 + t < deg) {
            int e = begin + c0 + t;
            ws[t] = expf(eattr[g_csr_eid[e]] - m) * inv;
            ss[t] = g_csr_src[e];
        }
        __syncthreads();
        int cn = min(128, deg - c0);
        int q = 0;
        for (; q + 4 <= cn; q += 4) {
            const float* x0 = &g_xt[(size_t)ss[q]   * FD];
            const float* x1 = &g_xt[(size_t)ss[q+1] * FD];
            const float* x2 = &g_xt[(size_t)ss[q+2] * FD];
            const float* x3 = &g_xt[(size_t)ss[q+3] * FD];
            float w0 = ws[q], w1 = ws[q+1], w2 = ws[q+2], w3 = ws[q+3];
            acc0 += w0*x0[o0] + w1*x1[o0] + w2*x2[o0] + w3*x3[o0];
            if (has1) acc1 += w0*x0[o1] + w1*x1[o1] + w2*x2[o1] + w3*x3[o1];
        }
        for (; q < cn; q++) {
            float wv = ws[q];
            const float* xr = &g_xt[(size_t)ss[q] * FD];
            acc0 += wv * xr[o0];
            if (has1) acc1 += wv * xr[o1];
        }
        __syncthreads();
    }
    acc0 += bias[o0];
    if (has1) acc1 += bias[o1];
    float* out = outsel ? g_h2 : g_h1;
    out[(size_t)d * FD + o0] = acc0;
    if (has1) out[(size_t)d * FD + o1] = acc1;

    float dp = acc0 * pw[o0] + (has1 ? acc1 * pw[o1] : 0.f);
    sred[t] = dp; __syncthreads();
    for (int s = 64; s; s >>= 1) { if (t < s) sred[t] += sred[t + s]; __syncthreads(); }
    if (t == 0) g_dp[half * NN + d] = sred[0];
}

// ======== sort: combine dot partials -> score -> bitonic ================
template<int STAGE>
__global__ void k_sort()
{
    constexpr int n_per = (STAGE == 1) ? NPn : KP1;
    constexpr int K     = (STAGE == 1) ? KP1 : KP2;
    int g = blockIdx.x;
    int t = threadIdx.x;                 // 512
    __shared__ float sc[512];
    __shared__ int   si[512];
    float invn = g_invn[STAGE - 1];
    if (t < n_per) {
        int node = g * n_per + t;
        float dp = g_dp[node] + g_dp[NN + node];
        sc[t] = 1.f / (1.f + expf(-dp * invn));
        si[t] = t;
    } else { sc[t] = -FLT_MAX; si[t] = 100000 + t; }
    if (STAGE == 1 && t < NPn) g_cnt[g * NPn + t] = 0;   // reset counters for stage 2
    __syncthreads();

    for (int k = 2; k <= 512; k <<= 1) {
        for (int j = k >> 1; j; j >>= 1) {
            int ixj = t ^ j;
            if (ixj > t) {
                float a = sc[t], b2 = sc[ixj];
                int ia = si[t], ib = si[ixj];
                bool afirst = (a > b2) || (a == b2 && ia < ib);
                bool up = ((t & k) == 0);
                if (up ? !afirst : afirst) { sc[t] = b2; sc[ixj] = a; si[t] = ib; si[ixj] = ia; }
            }
            __syncthreads();
        }
    }
    if (t < K) { g_si[g * 256 + t] = si[t]; g_sc[g * 256 + t] = sc[t]; }
    if (STAGE == 1) {
        if (t < n_per) g_newidx1[g * n_per + t] = -1;
        __syncthreads();
        if (t < K) {
            g_newidx1[g * n_per + si[t]] = g * K + t;
            g_perm1[g * K + t] = g * n_per + si[t];
        }
    }
}

// ======== fused: post1 readout (blocks 0-11) + count1 (blocks 12+) ======
// both depend only on sort1; mutually independent.
__global__ void __launch_bounds__(512) k_postcnt(const int* __restrict__ ei)
{
    int bx = blockIdx.x;
    int t  = threadIdx.x;
    if (bx >= 12) {                      // ---- count1 ----
        int e = (bx - 12) * 512 + t;
        if (e >= NE) return;
        int ns = g_newidx1[ei[e]];
        int nd = g_newidx1[ei[NE + e]];
        if (ns < 0 || nd < 0) return;
        atomicAdd(&g_cnt[nd], 1);
        return;
    }
    // ---- post1 readout ----
    constexpr int n_per = NPn, K = KP1;
    int g  = bx / 6;
    int cb = bx - g * 6;
    __shared__ float ssc[K];
    __shared__ int   ssi[K];
    for (int i = t; i < K; i += 512) { ssc[i] = g_sc[g * 256 + i]; ssi[i] = g_si[g * 256 + i]; }
    __syncthreads();
    int c  = cb * 64 + (t & 63);
    int rg = t >> 6;                              // 0..7
    float mx = -FLT_MAX, sm = 0.f;
    if (c < FD) {
#pragma unroll 4
        for (int r = rg; r < K; r += 8) {
            float v = g_h1[(size_t)(g * n_per + ssi[r]) * FD + c] * ssc[r];
            mx = fmaxf(mx, v); sm += v;
        }
    }
    __shared__ float smax[512], ssum[512];
    smax[t] = mx; ssum[t] = sm;
    __syncthreads();
    if (rg == 0 && c < FD) {
        float M0 = mx, S0 = sm;
#pragma unroll
        for (int q = 1; q < 8; q++) {
            M0 = fmaxf(M0, smax[t + q * 64]);
            S0 += ssum[t + q * 64];
        }
        g_z[g * ZDIM + c]      = M0;
        g_z[g * ZDIM + FD + c] = S0 / (float)K;
    }
}

// ======== post2: readout only ===========================================
__global__ void __launch_bounds__(512) k_post2()
{
    constexpr int n_per = KP1, K = KP2, zoff = 2 * FD;
    int g = blockIdx.y;
    int t = threadIdx.x;
    __shared__ float ssc[K];
    __shared__ int   ssi[K];
    for (int i = t; i < K; i += 512) { ssc[i] = g_sc[g * 256 + i]; ssi[i] = g_si[g * 256 + i]; }
    __syncthreads();
    int c  = blockIdx.x * 64 + (t & 63);
    int rg = t >> 6;
    float mx = -FLT_MAX, sm = 0.f;
    if (c < FD) {
#pragma unroll 4
        for (int r = rg; r < K; r += 8) {
            float v = g_h2[(size_t)(g * n_per + ssi[r]) * FD + c] * ssc[r];
            mx = fmaxf(mx, v); sm += v;
        }
    }
    __shared__ float smax[512], ssum[512];
    smax[t] = mx; ssum[t] = sm;
    __syncthreads();
    if (rg == 0 && c < FD) {
        float M0 = mx, S0 = sm;
#pragma unroll
        for (int q = 1; q < 8; q++) {
            M0 = fmaxf(M0, smax[t + q * 64]);
            S0 += ssum[t + q * 64];
        }
        g_z[g * ZDIM + zoff + c]      = M0;
        g_z[g * ZDIM + zoff + FD + c] = S0 / (float)K;
    }
}

// ======== fused MLP head (single block) + cleanup =======================
__global__ void k_head(const float* __restrict__ fc1W, const float* __restrict__ fc1b,
                       const float* __restrict__ bn1g, const float* __restrict__ bn1b,
                       const float* __restrict__ fc2W, const float* __restrict__ fc2b,
                       const float* __restrict__ bn2g, const float* __restrict__ bn2b,
                       const float* __restrict__ fc3W, const float* __restrict__ fc3b,
                       float* __restrict__ out)
{
    int t = threadIdx.x;                 // 352
    __shared__ float sz[2 * ZDIM];
    __shared__ float s1[2 * FD];
    __shared__ float s2[2 * DD3];
    for (int i = t; i < 2 * ZDIM; i += 352) sz[i] = g_z[i];
    for (int i = t; i < NN; i += 352) g_cnt[i] = 0;   // reset for next replay
    __syncthreads();

    if (t < FD) {
        float a0 = 0.f, a1 = 0.f;
        for (int i = 0; i < ZDIM; i++) {
            float wv = fc1W[(size_t)i * FD + t];
            a0 += sz[i] * wv;
            a1 += sz[ZDIM + i] * wv;
        }
        a0 += fc1b[t]; a1 += fc1b[t];
        float mn = 0.5f * (a0 + a1);
        float v  = 0.5f * ((a0 - mn)*(a0 - mn) + (a1 - mn)*(a1 - mn));
        float is = rsqrtf(v + 1e-5f);
        s1[t]      = fmaxf((a0 - mn) * is * bn1g[t] + bn1b[t], 0.f);
        s1[FD + t] = fmaxf((a1 - mn) * is * bn1g[t] + bn1b[t], 0.f);
    }
    __syncthreads();
    if (t < DD3) {
        float a0 = 0.f, a1 = 0.f;
        for (int i = 0; i < FD; i++) {
            float wv = fc2W[(size_t)i * DD3 + t];
            a0 += s1[i] * wv;
            a1 += s1[FD + i] * wv;
        }
        a0 += fc2b[t]; a1 += fc2b[t];
        float mn = 0.5f * (a0 + a1);
        float v  = 0.5f * ((a0 - mn)*(a0 - mn) + (a1 - mn)*(a1 - mn));
        float is = rsqrtf(v + 1e-5f);
        s2[t]       = fmaxf((a0 - mn) * is * bn2g[t] + bn2b[t], 0.f);
        s2[DD3 + t] = fmaxf((a1 - mn) * is * bn2g[t] + bn2b[t], 0.f);
    }
    __syncthreads();
    if (t < 2) {
        float a0 = 0.f, a1 = 0.f;
        for (int i = 0; i < DD3; i++) {
            float wv = fc3W[i*2 + t];
            a0 += s2[i] * wv;
            a1 += s2[DD3 + i] * wv;
        }
        out[t]     = a0 + fc3b[t];
        out[2 + t] = a1 + fc3b[t];
    }
}

// ---------------- launch -------------------------------------------------
extern "C" void kernel_launch(void* const* d_in, const int* in_sizes, int n_in,
                              void* d_out, int out_size)
{
    const float* x     = (const float*)d_in[0];
    const int*   ei    = (const int*)  d_in[1];
    const float* eattr = (const float*)d_in[3];
    const float* c1W1  = (const float*)d_in[6];
    const float* c1W2  = (const float*)d_in[7];
    const float* c1nb  = (const float*)d_in[8];
    const float* c1b   = (const float*)d_in[9];
    const float* p1w   = (const float*)d_in[10];
    const float* c2W1  = (const float*)d_in[11];
    const float* c2W2  = (const float*)d_in[12];
    const float* c2nb  = (const float*)d_in[13];
    const float* c2b   = (const float*)d_in[14];
    const float* p2w   = (const float*)d_in[15];
    const float* fc1W  = (const float*)d_in[16];
    const float* fc1b  = (const float*)d_in[17];
    const float* bn1g  = (const float*)d_in[18];
    const float* bn1b  = (const float*)d_in[19];
    const float* fc2W  = (const float*)d_in[20];
    const float* fc2b  = (const float*)d_in[21];
    const float* bn2g  = (const float*)d_in[22];
    const float* bn2b  = (const float*)d_in[23];
    const float* fc3W  = (const float*)d_in[24];
    const float* fc3b  = (const float*)d_in[25];
    float* out = (float*)d_out;

    constexpr int RED0 = (NN * FD / 4 + 255) / 256;       // 216
    constexpr int RED1 = (Gg * KP1 * FD / 4 + 255) / 256; // 108
    constexpr int FILLB = (NE + 255) / 256;               // 83

    // conv1
    k_count0<<<FILLB, 256>>>(ei);                                          // 1
    k_gemm<0><<<dim3(6, (NN + BM - 1) / BM, KSPL + 1), 128>>>(x, c1W1, c1W2, c1nb, p1w); // 2 (+scan0)
    k_redfill<0><<<RED0 + FILLB, 256>>>(ei);                               // 3 (reduce0+fill0)
    k_agg<<<dim3(NN, 2), 128>>>(0, eattr, c1b, p1w);                       // 4
    // pool1
    k_sort<1><<<Gg, 512>>>();                                              // 5
    k_postcnt<<<12 + (NE + 511) / 512, 512>>>(ei);                         // 6 (post1+count1)
    // conv2
    k_gemm<1><<<dim3(6, (Gg*KP1 + BM - 1) / BM, KSPL + 1), 128>>>(x, c2W1, c2W2, c2nb, p2w); // 7 (+scan1)
    k_redfill<1><<<RED1 + FILLB, 256>>>(ei);                               // 8 (reduce1+fill1)
    k_agg<<<dim3(Gg*KP1, 2), 128>>>(1, eattr, c2b, p2w);                   // 9
    // pool2
    k_sort<2><<<Gg, 512>>>();                                              // 10
    k_post2<<<dim3(6, Gg), 512>>>();                                       // 11
    // head
    k_head<<<1, 352>>>(fc1W, fc1b, bn1g, bn1b, fc2W, fc2b, bn2g, bn2b, fc3W, fc3b, out); // 12
}